// round 11
// baseline (speedup 1.0000x reference)
#include <cuda_runtime.h>
#include <math.h>
#include <stdint.h>

#define N_IN  32768
#define KC    4096
#define DIM   256
#define M_TILE 128
#define NT_COLS 64
#define N_NT   (KC / NT_COLS)            // 64 N-tiles; full K per tile
#define STAGES 3
#define STG_BYTES (NT_COLS * DIM)        // 16KB per B stage (64 cols x 256 i8)
#define A_BYTES  (M_TILE * DIM)          // 32KB resident A (2 chunks of 16KB)
#define EPS 1.5e-3f
#define DEQ 4.76837158203125e-07f        // 2^-21 = 2 / (16 * 2^18)

// ---- scratch (device globals; no allocation allowed) ----
__device__ uint8_t g_Xi8[(size_t)N_IN * DIM];   // 8MB  int8(round(16 x))
__device__ uint8_t g_Wi8[(size_t)KC   * DIM];   // 1MB  int8(round(2^18 w))
__device__ float  g_A[N_IN];
__device__ float  g_B[KC];
__device__ int    g_argmin[N_IN];
__device__ int    g_counts[KC];
__device__ double g_partial[512];

// ===========================================================================
// helpers
// ===========================================================================
__device__ __forceinline__ uint32_t smem_u32(const void* p) {
    uint32_t a;
    asm("{ .reg .u64 t; cvta.to.shared.u64 t, %1; cvt.u32.u64 %0, t; }" : "=r"(a) : "l"(p));
    return a;
}
#define CP_ASYNC16(dst, src) \
    asm volatile("cp.async.cg.shared.global [%0], [%1], 16;" :: "r"(dst), "l"(src) : "memory")
#define CP_COMMIT() asm volatile("cp.async.commit_group;" ::: "memory")

__device__ __forceinline__ uint32_t swz(uint32_t off) { return off ^ ((off >> 3) & 0x70); }

__device__ __forceinline__ void ldsm4(uint32_t* r, uint32_t addr) {
    asm volatile("ldmatrix.sync.aligned.m8n8.x4.shared.b16 {%0,%1,%2,%3}, [%4];"
        : "=r"(r[0]), "=r"(r[1]), "=r"(r[2]), "=r"(r[3]) : "r"(addr));
}
// s8 x s8 -> s32, m16n8k32 (exact integer dot)
__device__ __forceinline__ void mma_s8(int* c, const uint32_t* a, uint32_t b0, uint32_t b1) {
    asm volatile("mma.sync.aligned.m16n8k32.row.col.s32.s8.s8.s32 "
        "{%0,%1,%2,%3}, {%4,%5,%6,%7}, {%8,%9}, {%0,%1,%2,%3};"
        : "+r"(c[0]), "+r"(c[1]), "+r"(c[2]), "+r"(c[3])
        : "r"(a[0]), "r"(a[1]), "r"(a[2]), "r"(a[3]), "r"(b0), "r"(b1));
}
__device__ __forceinline__ bool lex_less(float v1, int i1, float v2, int i2) {
    return v1 < v2 || (v1 == v2 && i1 < i2);
}

// ===========================================================================
// small kernels
// ===========================================================================
__global__ void init_kernel() {
    int t = blockIdx.x * blockDim.x + threadIdx.x;
    if (t < KC) g_counts[t] = 0;
}

// fused int8 convert (with scale) + row norms (EXACT same reduction order)
__global__ void prep_kernel(const float* __restrict__ src, uint8_t* __restrict__ dst,
                            float* __restrict__ norms, int nrows, float scale) {
    int warp = (blockIdx.x * blockDim.x + threadIdx.x) >> 5;
    int lane = threadIdx.x & 31;
    if (warp >= nrows) return;
    const float* r = src + (size_t)warp * DIM;

    // norms: element order lane + i*32, sequential adds, shfl tree (unchanged)
    float s = 0.f;
    #pragma unroll
    for (int i = 0; i < DIM / 32; i++) {
        float v = r[lane + i * 32];
        s = __fadd_rn(s, __fmul_rn(v, v));
    }
    #pragma unroll
    for (int o = 16; o > 0; o >>= 1)
        s = __fadd_rn(s, __shfl_xor_sync(0xffffffffu, s, o));
    if (lane == 0) norms[warp] = s;

    // int8 conversion: word j covers elems 4j..4j+3
    uint32_t* d32 = (uint32_t*)(dst + (size_t)warp * DIM);
    #pragma unroll
    for (int i = 0; i < DIM / 128; i++) {
        int j = lane + i * 32;
        uint32_t packed = 0;
        #pragma unroll
        for (int b = 0; b < 4; b++) {
            int q = __float2int_rn(r[4 * j + b] * scale);
            q = max(-127, min(127, q));
            packed |= ((uint32_t)q & 0xffu) << (b * 8);
        }
        d32[j] = packed;
    }
}

// ===========================================================================
// int8 mma.sync distance GEMM + top-3 shortlist + exact fp32 refine
// CTA: 256 threads, 8 warps (4m x 2n), warp tile 32x32, CTA tile 128 rows.
// A (32KB i8) resident; B streamed as 64 whole N-tiles (16KB = full K=256).
// Race-free order: wait -> sync -> issue t+2 -> mma t. 80KB smem, 2 CTAs/SM.
// Fused zeroing of this CTA's 128 encoding rows.
// ===========================================================================
__global__ __launch_bounds__(256, 2)
void gemm_mma_kernel(const float* __restrict__ x, const float* __restrict__ w,
                     float* __restrict__ out_enc) {
    extern __shared__ char smem[];
    const uint32_t sbase = smem_u32(smem);
    const int tid  = threadIdx.x;
    const int wid  = tid >> 5;
    const int lane = tid & 31;
    const int warp_m = wid & 3;       // 32-row slab (0..3)
    const int warp_n = wid >> 2;      // 32-col slab (0..1)
    const int row0 = blockIdx.x * M_TILE;

    const uint32_t A_OFF = 0;                    // 32KB: 2 chunks of 16KB (k-halves)
    const uint32_t B_OFF = A_BYTES;              // 48KB: 3 stages of 16KB

    // enc slice for this CTA: rows [row0, row0+128)
    float* enc_slice = out_enc + (size_t)row0 * KC;
    float4* encz = (float4*)(enc_slice + 2);     // 16B-aligned (base is 8-mod-16)
    const int N_F4 = (M_TILE * KC - 4) / 4;      // 131071

    // ldmatrix per-lane geometry (8-bit k32 fragments; same as fp8 path)
    const int a_row_l = (((lane >> 3) & 1) << 3) + (lane & 7);
    const int a_seg   = (lane >> 4) << 4;
    const int b_n_l   = ((lane >> 4) << 3) + (lane & 7);
    const int b_seg   = ((lane >> 3) & 1) << 4;

    int acc[2][4][4];
    #pragma unroll
    for (int mi = 0; mi < 2; mi++)
        #pragma unroll
        for (int ni = 0; ni < 4; ni++)
            #pragma unroll
            for (int q = 0; q < 4; q++) acc[mi][ni][q] = 0;

    // top-3 per local row (4 local rows per thread), lex-sorted ascending.
    // approx metric omits the per-row A term (constant within a row).
    float cv[4][3];
    int   ci[4][3];
    #pragma unroll
    for (int lr = 0; lr < 4; lr++) {
        cv[lr][0] = cv[lr][1] = cv[lr][2] = 3.4e38f;
        ci[lr][0] = ci[lr][1] = ci[lr][2] = 0x7fffffff;
    }

    const uint8_t* xs = g_Xi8 + (size_t)row0 * DIM;

    // ---- load resident A (2 chunks x 16KB: rows x 128B k-halves) ----
    #pragma unroll
    for (int blk = 0; blk < 2; blk++) {
        const uint32_t Ab = sbase + A_OFF + blk * 16384;
        const uint8_t* ga = xs + blk * 128;
        #pragma unroll
        for (int i = 0; i < 4; i++) {
            int id = tid + i * 256;
            int r = id >> 3, k8 = id & 7;
            CP_ASYNC16(Ab + swz(r * 128 + k8 * 16), ga + (size_t)r * DIM + k8 * 16);
        }
    }
    CP_COMMIT();

    // ---- B tile issue: 64 cols x 256B as 2 sub-blocks (k-halves) of 8KB ----
    #define ISSUE_B(tt_) do {                                                 \
        const int s_ = (tt_) % 3;                                             \
        const uint32_t Bst_ = sbase + B_OFF + s_ * STG_BYTES;                 \
        const uint8_t* gb0_ = g_Wi8 + (size_t)((tt_) * NT_COLS) * DIM;        \
        _Pragma("unroll")                                                     \
        for (int sub = 0; sub < 2; sub++) {                                   \
            const uint32_t Bb_ = Bst_ + sub * 8192;                           \
            const uint8_t* gb_ = gb0_ + sub * 128;                            \
            _Pragma("unroll")                                                 \
            for (int i = 0; i < 2; i++) {                                     \
                int id = tid + i * 256;                                       \
                int r = id >> 3, k8 = id & 7;                                 \
                CP_ASYNC16(Bb_ + swz(r * 128 + k8 * 16), gb_ + (size_t)r * DIM + k8 * 16); \
            }                                                                 \
        }                                                                     \
        CP_COMMIT();                                                          \
    } while (0)

    ISSUE_B(0);
    ISSUE_B(1);

    #pragma unroll 1
    for (int t = 0; t < N_NT; t++) {
        if (t + 1 < N_NT) asm volatile("cp.async.wait_group 1;" ::: "memory");
        else              asm volatile("cp.async.wait_group 0;" ::: "memory");
        __syncthreads();
        if (t + 2 < N_NT) ISSUE_B(t + 2);

        // fused enc zeroing: 8 coalesced float4 stores per thread per tile
        {
            const float4 z4 = make_float4(0.f, 0.f, 0.f, 0.f);
            const int base = t * 2048 + tid;
            #pragma unroll
            for (int j = 0; j < 8; j++) {
                int idx = base + j * 256;
                if (idx < N_F4) encz[idx] = z4;
            }
            if (t == 0 && tid == 0) {
                enc_slice[0] = 0.f; enc_slice[1] = 0.f;
                enc_slice[(size_t)M_TILE * KC - 2] = 0.f;
                enc_slice[(size_t)M_TILE * KC - 1] = 0.f;
            }
        }

        const uint32_t Bst = sbase + B_OFF + (t % 3) * STG_BYTES;

        // full K = 8 steps of k32
        #pragma unroll
        for (int step = 0; step < 8; step++) {
            const uint32_t Ab = sbase + A_OFF + (step >> 2) * 16384;
            const uint32_t Bb = Bst + (step >> 2) * 8192;
            const int kb = (step & 3) * 32;
            uint32_t af[2][4];
            #pragma unroll
            for (int mi = 0; mi < 2; mi++)
                ldsm4(af[mi], Ab + swz((warp_m * 32 + mi * 16 + a_row_l) * 128
                                       + kb + a_seg));
            uint32_t bf[2][4];
            #pragma unroll
            for (int pp = 0; pp < 2; pp++)
                ldsm4(bf[pp], Bb + swz((warp_n * 32 + pp * 16 + b_n_l) * 128
                                       + kb + b_seg));
            #pragma unroll
            for (int mi = 0; mi < 2; mi++)
                #pragma unroll
                for (int ni = 0; ni < 4; ni++)
                    mma_s8(acc[mi][ni], af[mi],
                           bf[ni >> 1][(ni & 1) * 2], bf[ni >> 1][(ni & 1) * 2 + 1]);
        }

        // N-tile finished: approx v' = B[col] - acc*2^-21, maintain top-3
        {
            const int colbase = t * NT_COLS + warp_n * 32;
            #pragma unroll
            for (int mi = 0; mi < 2; mi++)
                #pragma unroll
                for (int h = 0; h < 2; h++) {
                    const int lr = mi * 2 + h;
                    #pragma unroll
                    for (int ni = 0; ni < 4; ni++)
                        #pragma unroll
                        for (int cc = 0; cc < 2; cc++) {
                            const int col = colbase + ni * 8 + 2 * (lane & 3) + cc;
                            float d = (float)acc[mi][ni][h * 2 + cc];
                            float v = __fsub_rn(g_B[col], d * DEQ);
                            if (lex_less(v, col, cv[lr][2], ci[lr][2])) {
                                if (lex_less(v, col, cv[lr][1], ci[lr][1])) {
                                    cv[lr][2] = cv[lr][1]; ci[lr][2] = ci[lr][1];
                                    if (lex_less(v, col, cv[lr][0], ci[lr][0])) {
                                        cv[lr][1] = cv[lr][0]; ci[lr][1] = ci[lr][0];
                                        cv[lr][0] = v;         ci[lr][0] = col;
                                    } else {
                                        cv[lr][1] = v;         ci[lr][1] = col;
                                    }
                                } else {
                                    cv[lr][2] = v;             ci[lr][2] = col;
                                }
                            }
                            acc[mi][ni][h * 2 + cc] = 0;
                        }
                }
        }
    }

    // gather shortlist to smem (reuse A region): 128 rows x 24 entries
    __syncthreads();
    float* redv = (float*)smem;                    // 12KB
    int*   redi = (int*)(smem + 128 * 24 * 4);     // 12KB
    #pragma unroll
    for (int lr = 0; lr < 4; lr++) {
        int mi = lr >> 1, h = lr & 1;
        const int row = warp_m * 32 + mi * 16 + h * 8 + (lane >> 2);
        const int slot = (warp_n * 4 + (lane & 3)) * 3;
        #pragma unroll
        for (int j = 0; j < 3; j++) {
            redv[row * 24 + slot + j] = cv[lr][j];
            redi[row * 24 + slot + j] = ci[lr][j];
        }
    }
    __syncthreads();

    // exact fp32 refine: one thread per row (sequential fmaf order = R1-proven)
    if (tid < M_TILE) {
        const int row = row0 + tid;
        float gmin = 3.4e38f;
        #pragma unroll
        for (int j = 0; j < 24; j++)
            gmin = fminf(gmin, redv[tid * 24 + j]);
        const float thresh = gmin + EPS;
        const float Ar = g_A[row];
        const float* xr = x + (size_t)row * DIM;

        float bestv = 3.4e38f;
        int   besti = 0x7fffffff;
        for (int j = 0; j < 24; j++) {
            float va = redv[tid * 24 + j];
            int   col = redi[tid * 24 + j];
            if (va > thresh || col == 0x7fffffff) continue;
            const float* wr = w + (size_t)col * DIM;
            float dot = 0.f;
            #pragma unroll 8
            for (int k = 0; k < DIM; k++)
                dot = fmaf(xr[k], __ldg(wr + k), dot);
            float u = __fadd_rn(Ar, g_B[col]);
            float ve = __fsub_rn(u, __fmul_rn(2.0f, dot));
            if (lex_less(ve, col, bestv, besti)) { bestv = ve; besti = col; }
        }
        g_argmin[row] = besti;
    }
}

// ===========================================================================
// epilogue + finalize
// ===========================================================================
__global__ __launch_bounds__(256)
void epilogue_kernel(const float* __restrict__ x, const float* __restrict__ w,
                     float* __restrict__ out_qst, float* __restrict__ out_enc) {
    __shared__ double sred[256];
    const int tid = threadIdx.x;
    const int rowLocal = tid >> 2;
    const int sub = tid & 3;
    const int row = blockIdx.x * 64 + rowLocal;
    const int idx = g_argmin[row];

    const float* wr = w + (size_t)idx * DIM;
    const float* xr = x + (size_t)row * DIM;
    float* qr = out_qst + (size_t)row * DIM;

    double ls = 0.0;
    #pragma unroll 8
    for (int u = 0; u < DIM / 4; u++) {
        int e = u * 4 + sub;
        float wv = wr[e];
        float xv = xr[e];
        float dlt = __fsub_rn(wv, xv);
        qr[e] = __fadd_rn(xv, dlt);
        float t = __fmul_rn(dlt, dlt);
        ls += (double)t;
    }
    if (sub == 0) {
        out_enc[(size_t)row * KC + idx] = 1.0f;
        atomicAdd(&g_counts[idx], 1);
    }
    sred[tid] = ls;
    __syncthreads();
    #pragma unroll
    for (int s = 128; s > 0; s >>= 1) {
        if (tid < s) sred[tid] += sred[tid + s];
        __syncthreads();
    }
    if (tid == 0) g_partial[blockIdx.x] = sred[0];
}

__global__ __launch_bounds__(256)
void finalize_kernel(float* __restrict__ out_loss, float* __restrict__ out_perp) {
    __shared__ double sred[256];
    const int tid = threadIdx.x;

    double s = g_partial[tid] + g_partial[tid + 256];
    sred[tid] = s;
    __syncthreads();
    #pragma unroll
    for (int st = 128; st > 0; st >>= 1) {
        if (tid < st) sred[tid] += sred[tid + st];
        __syncthreads();
    }
    if (tid == 0) {
        double total = sred[0];
        float m = (float)(total / (double)((long long)N_IN * DIM));
        *out_loss = __fadd_rn(m, __fmul_rn(0.25f, m));
    }
    __syncthreads();

    double ps = 0.0;
    #pragma unroll
    for (int i = 0; i < KC / 256; i++) {
        int k = tid + i * 256;
        float p = (float)g_counts[k] * (1.0f / (float)N_IN);
        float term = p * logf(__fadd_rn(p, 1e-10f));
        ps += (double)term;
    }
    sred[tid] = ps;
    __syncthreads();
    #pragma unroll
    for (int st = 128; st > 0; st >>= 1) {
        if (tid < st) sred[tid] += sred[tid + st];
        __syncthreads();
    }
    if (tid == 0) *out_perp = expf((float)(-sred[0]));
}

// ===========================================================================
extern "C" void kernel_launch(void* const* d_in, const int* in_sizes, int n_in,
                              void* d_out, int out_size) {
    const float* x = (const float*)d_in[0];
    const float* w = (const float*)d_in[1];
    if (n_in >= 2 && in_sizes[0] == KC * DIM && in_sizes[1] == N_IN * DIM) {
        x = (const float*)d_in[1];
        w = (const float*)d_in[0];
    }

    float* out = (float*)d_out;
    float* out_loss = out;
    float* out_qst  = out + 1;
    float* out_perp = out + 1 + (size_t)N_IN * DIM;
    float* out_enc  = out + 2 + (size_t)N_IN * DIM;

    uint8_t* xi8 = nullptr; uint8_t* wi8 = nullptr;
    float* ga = nullptr; float* gb = nullptr;
    cudaGetSymbolAddress((void**)&xi8, g_Xi8);
    cudaGetSymbolAddress((void**)&wi8, g_Wi8);
    cudaGetSymbolAddress((void**)&ga, g_A);
    cudaGetSymbolAddress((void**)&gb, g_B);

    const int SMEM_BYTES = A_BYTES + STAGES * STG_BYTES;   // 80KB
    cudaFuncSetAttribute(gemm_mma_kernel, cudaFuncAttributeMaxDynamicSharedMemorySize, SMEM_BYTES);

    init_kernel<<<(KC + 255) / 256, 256>>>();
    prep_kernel<<<N_IN / 8, 256>>>(x, xi8, ga, N_IN, 16.0f);       // 2^4
    prep_kernel<<<KC / 8, 256>>>(w, wi8, gb, KC, 262144.0f);       // 2^18

    gemm_mma_kernel<<<N_IN / M_TILE, 256, SMEM_BYTES>>>(x, w, out_enc);

    epilogue_kernel<<<N_IN / 64, 256>>>(x, w, out_qst, out_enc);
    finalize_kernel<<<1, 256>>>(out_loss, out_perp);
}